// round 16
// baseline (speedup 1.0000x reference)
#include <cuda_runtime.h>
#include <cuda_fp16.h>
#include <cstdint>
#include <math.h>

#define H 2048
#define E 64
#define BM 64
#define NKK (H / 16)    // 128 k16 steps
#define NCH (H / 64)    // 32 chunks of 64 k
#define LSCALE 4096.0f
#define LINV   (1.0f / 4096.0f)

// dynamic smem layout (per CTA):
//   [0, 32768)      fp16 A planes: buf b at b*16384, plane p at +p*8192
//   [32768, 98304)  B ring: stage s (0..3) at 32768 + s*16384
#define BR_OFF 32768
#define SMEM_DYN 98304

// ---------------- device globals (no allocation allowed) -------------------
__device__ float g_bias[E];
__device__ float g_cnt[E];
__device__ float g_psum[E];
__device__ unsigned g_done;
// W planes prepacked in mma B-fragment per-lane order:
// index = (kk*8 + gtile)*32 + lane ; {h_b0, h_b1, lScaled_b0, lScaled_b1}
__device__ uint4 g_wp[NKK * 8 * 32];

// ---------------- helpers ---------------------------------------------------
__device__ __forceinline__ uint32_t smem_u32(const void* p) {
    uint32_t a;
    asm("{ .reg .u64 t; cvta.to.shared.u64 t, %1; cvt.u32.u64 %0, t; }" : "=r"(a) : "l"(p));
    return a;
}

__device__ __forceinline__ void cpa16(uint32_t dst, const void* src) {
    asm volatile("cp.async.cg.shared.global [%0], [%1], 16;" :: "r"(dst), "l"(src));
}
#define CP_COMMIT() asm volatile("cp.async.commit_group;" ::: "memory")
#define CP_WAIT2()  asm volatile("cp.async.wait_group 2;" ::: "memory")

// split (f0,f1) -> fp16x2 hi plane + fp16x2 lo plane scaled by 2^12
__device__ __forceinline__ void splitH(float f0, float f1, uint32_t& h, uint32_t& l) {
    __half2 hh = __floats2half2_rn(f0, f1);
    float2 hf = __half22float2(hh);
    __half2 ll = __floats2half2_rn((f0 - hf.x) * LSCALE, (f1 - hf.y) * LSCALE);
    h = *(uint32_t*)&hh;
    l = *(uint32_t*)&ll;
}

__device__ __forceinline__ void mma16816(float* c,
                                         uint32_t a0, uint32_t a1, uint32_t a2, uint32_t a3,
                                         uint32_t b0, uint32_t b1) {
    asm("mma.sync.aligned.m16n8k16.row.col.f32.f16.f16.f32 "
        "{%0,%1,%2,%3}, {%4,%5,%6,%7}, {%8,%9}, {%0,%1,%2,%3};"
        : "+f"(c[0]), "+f"(c[1]), "+f"(c[2]), "+f"(c[3])
        : "r"(a0), "r"(a1), "r"(a2), "r"(a3), "r"(b0), "r"(b1));
}

__device__ __forceinline__ void ldm4(uint32_t& r0, uint32_t& r1,
                                     uint32_t& r2, uint32_t& r3, uint32_t addr) {
    asm volatile("ldmatrix.sync.aligned.m8n8.x4.shared.b16 {%0,%1,%2,%3}, [%4];"
                 : "=r"(r0), "=r"(r1), "=r"(r2), "=r"(r3) : "r"(addr));
}

__device__ __forceinline__ uint4 lds128(uint32_t addr) {
    uint4 v;
    asm volatile("ld.shared.v4.u32 {%0,%1,%2,%3}, [%4];"
                 : "=r"(v.x), "=r"(v.y), "=r"(v.z), "=r"(v.w) : "r"(addr));
    return v;
}

// ---------------------------------------------------------------------------
// W prep (+ bias init + accumulator reset, folded into block 0)
__global__ __launch_bounds__(256) void wprep_kernel(const float* __restrict__ W,
                                                    const float* __restrict__ rep,
                                                    const float* __restrict__ loads,
                                                    const float* __restrict__ counts,
                                                    const int* __restrict__ total) {
    int id = blockIdx.x * 256 + threadIdx.x;   // 0..32767
    int lane = id & 31;
    int gt = (id >> 5) & 7;
    int kk = id >> 8;
    int n = gt * 8 + (lane >> 2);
    int q = lane & 3;
    int p0 = n * (H / 2) + kk * 8 + q;   // pair index into W
    int p1 = p0 + 4;
    float2 f0 = ((const float2*)W)[p0];
    float2 f1 = ((const float2*)W)[p1];
    uint32_t h0, l0, h1, l1;
    splitH(f0.x, f0.y, h0, l0);
    splitH(f1.x, f1.y, h1, l1);
    g_wp[id] = make_uint4(h0, h1, l0, l1);

    if (blockIdx.x == 0) {
        int t = threadIdx.x;
        if (t < E) {
            float lt = logf((float)(*total) + 1.0f);
            float expl = 0.1f * sqrtf(lt / (counts[t] + 1e-10f));
            float ul = 0.9f * loads[t] + 0.1f * loads[t];   // mirror reference EMA
            g_bias[t] = 0.1f * rep[t] - 0.1f * ul + expl;
            g_cnt[t] = 0.0f;
            g_psum[t] = 0.0f;
        }
        if (t == 64) g_done = 0u;
    }
}

// ---------------------------------------------------------------------------
// R10 GEMM with deeper B pipeline: A via register prefetch + smem fp16 planes
// (double-buffered, swizzled); B via cp.async 4-stage smem ring issued 3
// chunks ahead (wait_group 2 after the MMA loop); ldmatrix consumers; fused
// top-2/softmax/aux epilogue.
// 8 warps = (mg 0..1: m32) x (ng 0..1: n32) x (ks 0..1: k16-steps of chunk).
// fp16 A: buf b, plane p at b*16384 + p*8192; row r stride 128B;
//   16B quad qq (0..7, = 8 k) stored at slot qq^(r&7).
// ---------------------------------------------------------------------------
__global__ __launch_bounds__(256, 2) void gemm_kernel(const float* __restrict__ X,
                                                      float* __restrict__ out, int T) {
    extern __shared__ __align__(128) char smA[];
    __shared__ float sS[BM][66];
    __shared__ float sB[E], sP[E], sC[E];
    __shared__ float sRed[64];
    __shared__ unsigned s_last;

    int tid = threadIdx.x, lane = tid & 31, wid = tid >> 5;
    int mg = wid & 1, ng = (wid >> 1) & 1, ks = wid >> 2;
    int q = lane & 3;
    if (tid < E) { sB[tid] = g_bias[tid]; sP[tid] = 0.0f; sC[tid] = 0.0f; }

    int tokBase = blockIdx.x * BM;
    uint32_t smb = smem_u32(smA);

    // ---- producer: row = tid/4, quad pair {pq, pq+4} (each quad = 8 k) ----
    int prow = tid >> 2, pq = tid & 3;
    const float4* xg = (const float4*)(X + (size_t)(tokBase + prow) * H) + pq * 2;
    uint32_t pOffA = (uint32_t)(prow * 128 + (((pq)     ^ (prow & 7)) << 4));
    uint32_t pOffB = (uint32_t)(prow * 128 + (((pq + 4) ^ (prow & 7)) << 4));

    // ---- B ring copy assignment: thread copies 4 consecutive uint4 ----
    const uint4* bsrc = g_wp + tid * 4;
    uint32_t bdst = smb + BR_OFF + (uint32_t)(tid * 64);

    // ---- consumer ldmatrix lane addressing ----
    int tRow = (lane >> 3) & 1;
    int tCq  = lane >> 4;            // 0/1 -> quad 2j + tCq
    int rB = mg * 32 + tRow * 8 + (lane & 7);
    int e7 = rB & 7;
    uint32_t cBase = smb + (uint32_t)(rB * 128);

    // consumer B smem base: gtile = ng*4 + t, addr = ((j*8 + gtile)*32 + lane)*16
    uint32_t bCons = smb + BR_OFF + (uint32_t)(((ng * 4) * 32 + lane) * 16);

    float acc[2][4][4], accL[2][4][4];
#pragma unroll
    for (int s = 0; s < 2; ++s)
#pragma unroll
        for (int t = 0; t < 4; ++t)
#pragma unroll
            for (int c = 0; c < 4; ++c) { acc[s][t][c] = 0.0f; accL[s][t][c] = 0.0f; }

    // ---- prologue: cp.async B chunks 0..2 FIRST (start DRAM early), then
    //      load+convert A chunk 0; wait_group 2 -> B chunk 0 resident ----
#pragma unroll
    for (int cc = 0; cc < 3; ++cc) {
        const uint4* src = bsrc + cc * 1024;
        uint32_t dst = bdst + (uint32_t)(cc * 16384);
#pragma unroll
        for (int i = 0; i < 4; ++i) cpa16(dst + i * 16, src + i);
        CP_COMMIT();
    }
    {
        float4 f0 = xg[0], f1 = xg[1], f2 = xg[8], f3 = xg[9];
        uint4 hA, lA, hB, lB;
        splitH(f0.x, f0.y, hA.x, lA.x); splitH(f0.z, f0.w, hA.y, lA.y);
        splitH(f1.x, f1.y, hA.z, lA.z); splitH(f1.z, f1.w, hA.w, lA.w);
        splitH(f2.x, f2.y, hB.x, lB.x); splitH(f2.z, f2.w, hB.y, lB.y);
        splitH(f3.x, f3.y, hB.z, lB.z); splitH(f3.z, f3.w, hB.w, lB.w);
        *(uint4*)(smA + pOffA)        = hA;
        *(uint4*)(smA + pOffA + 8192) = lA;
        *(uint4*)(smA + pOffB)        = hB;
        *(uint4*)(smA + pOffB + 8192) = lB;
    }
    CP_WAIT2();   // B chunk 0 resident (chunks 1,2 in flight)
    __syncthreads();

    float4 gr0, gr1, gr2, gr3;
    for (int c = 0; c < NCH; ++c) {
        // prefetch A regs for chunk c+1 (used in convert at end of this chunk)
        if (c + 1 < NCH) {
            gr0 = xg[(c + 1) * 16];
            gr1 = xg[(c + 1) * 16 + 1];
            gr2 = xg[(c + 1) * 16 + 8];
            gr3 = xg[(c + 1) * 16 + 9];
        }
        // issue cp.async for B chunk c+3 into stage (c+3)&3
        if (c + 3 < NCH) {
            const uint4* src = bsrc + (c + 3) * 1024;
            uint32_t dst = bdst + (uint32_t)(((c + 3) & 3) * 16384);
#pragma unroll
            for (int i = 0; i < 4; ++i) cpa16(dst + i * 16, src + i);
        }
        CP_COMMIT();

        uint32_t bufOff = (uint32_t)((c & 1) * 16384);
        uint32_t bStage = bCons + (uint32_t)((c & 3) * 16384);

#pragma unroll
        for (int jj = 0; jj < 2; ++jj) {
            int j = ks * 2 + jj;
            uint4 b[4];
#pragma unroll
            for (int t = 0; t < 4; ++t)
                b[t] = lds128(bStage + (uint32_t)((j * 8 + t) * 32 * 16));

            uint32_t sw = (uint32_t)((((2 * j + tCq) ^ e7) << 4));
            uint32_t ah[2][4], al[2][4];
#pragma unroll
            for (int s = 0; s < 2; ++s) {
                uint32_t addrH = cBase + bufOff + (uint32_t)(s * 16 * 128) + sw;
                ldm4(ah[s][0], ah[s][1], ah[s][2], ah[s][3], addrH);
                ldm4(al[s][0], al[s][1], al[s][2], al[s][3], addrH + 8192);
            }

#pragma unroll
            for (int t = 0; t < 4; ++t) {
                uint32_t bh0 = b[t].x, bh1 = b[t].y;
                uint32_t bl0 = b[t].z, bl1 = b[t].w;
#pragma unroll
                for (int s = 0; s < 2; ++s) {
                    mma16816(acc[s][t],  ah[s][0], ah[s][1], ah[s][2], ah[s][3], bh0, bh1);
                    mma16816(accL[s][t], ah[s][0], ah[s][1], ah[s][2], ah[s][3], bl0, bl1);
                    mma16816(accL[s][t], al[s][0], al[s][1], al[s][2], al[s][3], bh0, bh1);
                }
            }
        }

        // wait for B chunk c+1 (chunks c+2, c+3 stay in flight)
        CP_WAIT2();

        // convert + stage A chunk c+1 into the other fp16 buffer
        if (c + 1 < NCH) {
            uint4 hA, lA, hB, lB;
            splitH(gr0.x, gr0.y, hA.x, lA.x); splitH(gr0.z, gr0.w, hA.y, lA.y);
            splitH(gr1.x, gr1.y, hA.z, lA.z); splitH(gr1.z, gr1.w, hA.w, lA.w);
            splitH(gr2.x, gr2.y, hB.x, lB.x); splitH(gr2.z, gr2.w, hB.y, lB.y);
            splitH(gr3.x, gr3.y, hB.z, lB.z); splitH(gr3.z, gr3.w, hB.w, lB.w);
            uint32_t o = (uint32_t)(((c + 1) & 1) * 16384);
            *(uint4*)(smA + pOffA + o)        = hA;
            *(uint4*)(smA + pOffA + o + 8192) = lA;
            *(uint4*)(smA + pOffB + o)        = hB;
            *(uint4*)(smA + pOffB + o + 8192) = lB;
        }
        __syncthreads();
    }

    // ---- k-split reduction + scores into smem ----
    if (ks == 1) {
#pragma unroll
        for (int s = 0; s < 2; ++s) {
            int rr = mg * 32 + s * 16 + (lane >> 2);
#pragma unroll
            for (int t = 0; t < 4; ++t) {
                int cc = ng * 32 + t * 8 + 2 * q;
                *(float2*)&sS[rr][cc] = make_float2(
                    acc[s][t][0] + accL[s][t][0] * LINV,
                    acc[s][t][1] + accL[s][t][1] * LINV);
                *(float2*)&sS[rr + 8][cc] = make_float2(
                    acc[s][t][2] + accL[s][t][2] * LINV,
                    acc[s][t][3] + accL[s][t][3] * LINV);
            }
        }
    }
    __syncthreads();
    if (ks == 0) {
#pragma unroll
        for (int s = 0; s < 2; ++s) {
            int rr = mg * 32 + s * 16 + (lane >> 2);
#pragma unroll
            for (int t = 0; t < 4; ++t) {
                int cc = ng * 32 + t * 8 + 2 * q;
                float2 p0 = *(float2*)&sS[rr][cc];
                float2 p1 = *(float2*)&sS[rr + 8][cc];
                *(float2*)&sS[rr][cc] = make_float2(
                    p0.x + acc[s][t][0] + accL[s][t][0] * LINV,
                    p0.y + acc[s][t][1] + accL[s][t][1] * LINV);
                *(float2*)&sS[rr + 8][cc] = make_float2(
                    p1.x + acc[s][t][2] + accL[s][t][2] * LINV,
                    p1.y + acc[s][t][3] + accL[s][t][3] * LINV);
            }
        }
    }
    __syncthreads();

    // ---- per-token epilogue (threads 0..63, one token each) ----
    if (tid < BM) {
        float a = -1e30f, b = -1e30f;
        int ai = 0, bi = 0;
#pragma unroll
        for (int j = 0; j < 64; ++j) {
            float s = sS[tid][j] + sB[j];
            sS[tid][j] = s;
            if (s > a)      { b = a; bi = ai; a = s; ai = j; }
            else if (s > b) { b = s; bi = j; }
        }
        float sum = 0.0f;
#pragma unroll
        for (int j = 0; j < 64; ++j) {
            float e = __expf(sS[tid][j] - a);
            sS[tid][j] = e;
            sum += e;
        }
        float inv = 1.0f / sum;
#pragma unroll
        for (int j = 0; j < 64; ++j) sS[tid][j] *= inv;

        int tok = tokBase + tid;
        float tt = __expf(b - a);
        float w1 = 1.0f / (1.0f + tt);
        out[2 * tok]     = w1;
        out[2 * tok + 1] = tt * w1;
        out[2 * T + 2 * tok]     = (float)ai;
        out[2 * T + 2 * tok + 1] = (float)bi;
        atomicAdd(&sC[ai], 1.0f);
        atomicAdd(&sC[bi], 1.0f);
    }
    __syncthreads();

    // ---- per-expert prob column sums (all 256 threads, 4 slices of 16 rows) ----
    {
        int e = tid & 63, sl = tid >> 6;
        float s = 0.0f;
#pragma unroll
        for (int i = 0; i < 16; ++i)
            s += sS[sl * 16 + i][e];
        atomicAdd(&sP[e], s);
    }
    __syncthreads();
    if (tid < E) {
        atomicAdd(&g_psum[tid], sP[tid]);
        atomicAdd(&g_cnt[tid], sC[tid]);
    }

    // ---- last CTA computes aux loss ----
    if (tid == 0) {
        __threadfence();
        unsigned v = atomicAdd(&g_done, 1u);
        s_last = (v == gridDim.x - 1) ? 1u : 0u;
    }
    __syncthreads();
    if (s_last) {
        if (tid < 64) sRed[tid] = g_cnt[tid] * g_psum[tid];
    }
    __syncthreads();
    if (s_last && tid < 32) {
        float v = sRed[tid] + sRed[tid + 32];
#pragma unroll
        for (int off = 16; off > 0; off >>= 1)
            v += __shfl_xor_sync(0xffffffffu, v, off);
        if (tid == 0) {
            float invT = 1.0f / (float)T;
            out[4 * T] = v * 64.0f * invT * invT;
        }
    }
}

// ---------------------------------------------------------------------------
extern "C" void kernel_launch(void* const* d_in, const int* in_sizes, int n_in,
                              void* d_out, int out_size) {
    const float* x      = (const float*)d_in[0];
    const float* gw     = (const float*)d_in[1];
    const float* rep    = (const float*)d_in[2];
    const float* loads  = (const float*)d_in[3];
    const float* counts = (const float*)d_in[4];
    const int*   total  = (const int*)d_in[5];
    float* out = (float*)d_out;

    int T = in_sizes[0] / H;   // 16384

    cudaFuncSetAttribute(gemm_kernel, cudaFuncAttributeMaxDynamicSharedMemorySize, SMEM_DYN);

    wprep_kernel<<<NKK * 8 * 32 / 256, 256>>>(gw, rep, loads, counts, total);
    gemm_kernel<<<T / BM, 256, SMEM_DYN>>>(x, out, T);
}

// round 17
// speedup vs baseline: 1.2798x; 1.2798x over previous
#include <cuda_runtime.h>
#include <cuda_fp16.h>
#include <cstdint>
#include <math.h>

#define H 2048
#define E 64
#define BM 64
#define NKK (H / 16)    // 128 k16 steps
#define NCH (H / 64)    // 32 chunks of 64 k
#define LSCALE 4096.0f
#define LINV   (1.0f / 4096.0f)

// dynamic smem layout (per CTA):
//   [0, 32768)      fp16 A planes: buf b at b*16384, plane p at +p*8192
//   [32768, 98304)  B ring: stage s (0..3) at 32768 + s*16384
// epilogue (after final __syncthreads, aliased over dead A bufs):
//   sS 64x66 f32 at 0; bias at 16896; psum at 17152; cnt at 17408
#define BR_OFF 32768
#define SMEM_DYN 98304

// ---------------- device globals (no allocation allowed) -------------------
__device__ float g_bias[E];
__device__ float g_cnt[E];
__device__ float g_psum[E];
__device__ unsigned g_done;
// W planes prepacked in mma B-fragment per-lane order:
// index = (kk*8 + gtile)*32 + lane ; {h_b0, h_b1, lScaled_b0, lScaled_b1}
__device__ uint4 g_wp[NKK * 8 * 32];

// ---------------- helpers ---------------------------------------------------
__device__ __forceinline__ uint32_t smem_u32(const void* p) {
    uint32_t a;
    asm("{ .reg .u64 t; cvta.to.shared.u64 t, %1; cvt.u32.u64 %0, t; }" : "=r"(a) : "l"(p));
    return a;
}

__device__ __forceinline__ void cpa16(uint32_t dst, const void* src) {
    asm volatile("cp.async.cg.shared.global [%0], [%1], 16;" :: "r"(dst), "l"(src));
}
#define CP_COMMIT() asm volatile("cp.async.commit_group;" ::: "memory")
#define CP_WAIT2()  asm volatile("cp.async.wait_group 2;" ::: "memory")

// split (f0,f1) -> fp16x2 hi plane + fp16x2 lo plane scaled by 2^12
__device__ __forceinline__ void splitH(float f0, float f1, uint32_t& h, uint32_t& l) {
    __half2 hh = __floats2half2_rn(f0, f1);
    float2 hf = __half22float2(hh);
    __half2 ll = __floats2half2_rn((f0 - hf.x) * LSCALE, (f1 - hf.y) * LSCALE);
    h = *(uint32_t*)&hh;
    l = *(uint32_t*)&ll;
}

__device__ __forceinline__ void mma16816(float* c,
                                         uint32_t a0, uint32_t a1, uint32_t a2, uint32_t a3,
                                         uint32_t b0, uint32_t b1) {
    asm("mma.sync.aligned.m16n8k16.row.col.f32.f16.f16.f32 "
        "{%0,%1,%2,%3}, {%4,%5,%6,%7}, {%8,%9}, {%0,%1,%2,%3};"
        : "+f"(c[0]), "+f"(c[1]), "+f"(c[2]), "+f"(c[3])
        : "r"(a0), "r"(a1), "r"(a2), "r"(a3), "r"(b0), "r"(b1));
}

__device__ __forceinline__ void ldm4(uint32_t& r0, uint32_t& r1,
                                     uint32_t& r2, uint32_t& r3, uint32_t addr) {
    asm volatile("ldmatrix.sync.aligned.m8n8.x4.shared.b16 {%0,%1,%2,%3}, [%4];"
                 : "=r"(r0), "=r"(r1), "=r"(r2), "=r"(r3) : "r"(addr));
}

__device__ __forceinline__ uint4 lds128(uint32_t addr) {
    uint4 v;
    asm volatile("ld.shared.v4.u32 {%0,%1,%2,%3}, [%4];"
                 : "=r"(v.x), "=r"(v.y), "=r"(v.z), "=r"(v.w) : "r"(addr));
    return v;
}

// ---------------------------------------------------------------------------
// W prep (+ bias init + accumulator reset, folded into block 0)
__global__ __launch_bounds__(256) void wprep_kernel(const float* __restrict__ W,
                                                    const float* __restrict__ rep,
                                                    const float* __restrict__ loads,
                                                    const float* __restrict__ counts,
                                                    const int* __restrict__ total) {
    int id = blockIdx.x * 256 + threadIdx.x;   // 0..32767
    int lane = id & 31;
    int gt = (id >> 5) & 7;
    int kk = id >> 8;
    int n = gt * 8 + (lane >> 2);
    int q = lane & 3;
    int p0 = n * (H / 2) + kk * 8 + q;   // pair index into W
    int p1 = p0 + 4;
    float2 f0 = ((const float2*)W)[p0];
    float2 f1 = ((const float2*)W)[p1];
    uint32_t h0, l0, h1, l1;
    splitH(f0.x, f0.y, h0, l0);
    splitH(f1.x, f1.y, h1, l1);
    g_wp[id] = make_uint4(h0, h1, l0, l1);

    if (blockIdx.x == 0) {
        int t = threadIdx.x;
        if (t < E) {
            float lt = logf((float)(*total) + 1.0f);
            float expl = 0.1f * sqrtf(lt / (counts[t] + 1e-10f));
            float ul = 0.9f * loads[t] + 0.1f * loads[t];   // mirror reference EMA
            g_bias[t] = 0.1f * rep[t] - 0.1f * ul + expl;
            g_cnt[t] = 0.0f;
            g_psum[t] = 0.0f;
        }
        if (t == 64) g_done = 0u;
    }
}

// ---------------------------------------------------------------------------
// R10 GEMM + deeper B pipeline (4-stage ring, issued 3 ahead), epilogue smem
// aliased over dead A buffers so 2 CTAs/SM still fit (static smem ~0).
// 8 warps = (mg 0..1: m32) x (ng 0..1: n32) x (ks 0..1: k16-steps of chunk).
// fp16 A: buf b, plane p at b*16384 + p*8192; row r stride 128B;
//   16B quad qq (0..7, = 8 k) stored at slot qq^(r&7).
// ---------------------------------------------------------------------------
__global__ __launch_bounds__(256, 2) void gemm_kernel(const float* __restrict__ X,
                                                      float* __restrict__ out, int T) {
    extern __shared__ __align__(128) char smA[];
    __shared__ unsigned s_last;

    int tid = threadIdx.x, lane = tid & 31, wid = tid >> 5;
    int mg = wid & 1, ng = (wid >> 1) & 1, ks = wid >> 2;
    int q = lane & 3;

    int tokBase = blockIdx.x * BM;
    uint32_t smb = smem_u32(smA);

    // ---- producer: row = tid/4, quad pair {pq, pq+4} (each quad = 8 k) ----
    int prow = tid >> 2, pq = tid & 3;
    const float4* xg = (const float4*)(X + (size_t)(tokBase + prow) * H) + pq * 2;
    uint32_t pOffA = (uint32_t)(prow * 128 + (((pq)     ^ (prow & 7)) << 4));
    uint32_t pOffB = (uint32_t)(prow * 128 + (((pq + 4) ^ (prow & 7)) << 4));

    // ---- B ring copy assignment: thread copies 4 consecutive uint4 ----
    const uint4* bsrc = g_wp + tid * 4;
    uint32_t bdst = smb + BR_OFF + (uint32_t)(tid * 64);

    // ---- consumer ldmatrix lane addressing ----
    int tRow = (lane >> 3) & 1;
    int tCq  = lane >> 4;            // 0/1 -> quad 2j + tCq
    int rB = mg * 32 + tRow * 8 + (lane & 7);
    int e7 = rB & 7;
    uint32_t cBase = smb + (uint32_t)(rB * 128);

    // consumer B smem base: gtile = ng*4 + t, addr = ((j*8 + gtile)*32 + lane)*16
    uint32_t bCons = smb + BR_OFF + (uint32_t)(((ng * 4) * 32 + lane) * 16);

    float acc[2][4][4], accL[2][4][4];
#pragma unroll
    for (int s = 0; s < 2; ++s)
#pragma unroll
        for (int t = 0; t < 4; ++t)
#pragma unroll
            for (int c = 0; c < 4; ++c) { acc[s][t][c] = 0.0f; accL[s][t][c] = 0.0f; }

    // ---- prologue: cp.async B chunks 0..2 FIRST (start DRAM early), then
    //      load+convert A chunk 0; wait_group 2 -> B chunk 0 resident ----
#pragma unroll
    for (int cc = 0; cc < 3; ++cc) {
        const uint4* src = bsrc + cc * 1024;
        uint32_t dst = bdst + (uint32_t)(cc * 16384);
#pragma unroll
        for (int i = 0; i < 4; ++i) cpa16(dst + i * 16, src + i);
        CP_COMMIT();
    }
    {
        float4 f0 = xg[0], f1 = xg[1], f2 = xg[8], f3 = xg[9];
        uint4 hA, lA, hB, lB;
        splitH(f0.x, f0.y, hA.x, lA.x); splitH(f0.z, f0.w, hA.y, lA.y);
        splitH(f1.x, f1.y, hA.z, lA.z); splitH(f1.z, f1.w, hA.w, lA.w);
        splitH(f2.x, f2.y, hB.x, lB.x); splitH(f2.z, f2.w, hB.y, lB.y);
        splitH(f3.x, f3.y, hB.z, lB.z); splitH(f3.z, f3.w, hB.w, lB.w);
        *(uint4*)(smA + pOffA)        = hA;
        *(uint4*)(smA + pOffA + 8192) = lA;
        *(uint4*)(smA + pOffB)        = hB;
        *(uint4*)(smA + pOffB + 8192) = lB;
    }
    CP_WAIT2();   // B chunk 0 resident (chunks 1,2 in flight)
    __syncthreads();

    float4 gr0, gr1, gr2, gr3;
    for (int c = 0; c < NCH; ++c) {
        // prefetch A regs for chunk c+1 (used in convert at end of this chunk)
        if (c + 1 < NCH) {
            gr0 = xg[(c + 1) * 16];
            gr1 = xg[(c + 1) * 16 + 1];
            gr2 = xg[(c + 1) * 16 + 8];
            gr3 = xg[(c + 1) * 16 + 9];
        }
        // issue cp.async for B chunk c+3 into stage (c+3)&3
        if (c + 3 < NCH) {
            const uint4* src = bsrc + (c + 3) * 1024;
            uint32_t dst = bdst + (uint32_t)(((c + 3) & 3) * 16384);
#pragma unroll
            for (int i = 0; i < 4; ++i) cpa16(dst + i * 16, src + i);
        }
        CP_COMMIT();

        uint32_t bufOff = (uint32_t)((c & 1) * 16384);
        uint32_t bStage = bCons + (uint32_t)((c & 3) * 16384);

#pragma unroll
        for (int jj = 0; jj < 2; ++jj) {
            int j = ks * 2 + jj;
            uint4 b[4];
#pragma unroll
            for (int t = 0; t < 4; ++t)
                b[t] = lds128(bStage + (uint32_t)((j * 8 + t) * 32 * 16));

            uint32_t sw = (uint32_t)((((2 * j + tCq) ^ e7) << 4));
            uint32_t ah[2][4], al[2][4];
#pragma unroll
            for (int s = 0; s < 2; ++s) {
                uint32_t addrH = cBase + bufOff + (uint32_t)(s * 16 * 128) + sw;
                ldm4(ah[s][0], ah[s][1], ah[s][2], ah[s][3], addrH);
                ldm4(al[s][0], al[s][1], al[s][2], al[s][3], addrH + 8192);
            }

#pragma unroll
            for (int t = 0; t < 4; ++t) {
                uint32_t bh0 = b[t].x, bh1 = b[t].y;
                uint32_t bl0 = b[t].z, bl1 = b[t].w;
#pragma unroll
                for (int s = 0; s < 2; ++s) {
                    mma16816(acc[s][t],  ah[s][0], ah[s][1], ah[s][2], ah[s][3], bh0, bh1);
                    mma16816(accL[s][t], ah[s][0], ah[s][1], ah[s][2], ah[s][3], bl0, bl1);
                    mma16816(accL[s][t], al[s][0], al[s][1], al[s][2], al[s][3], bh0, bh1);
                }
            }
        }

        // wait for B chunk c+1 (chunks c+2, c+3 stay in flight)
        CP_WAIT2();

        // convert + stage A chunk c+1 into the other fp16 buffer
        if (c + 1 < NCH) {
            uint4 hA, lA, hB, lB;
            splitH(gr0.x, gr0.y, hA.x, lA.x); splitH(gr0.z, gr0.w, hA.y, lA.y);
            splitH(gr1.x, gr1.y, hA.z, lA.z); splitH(gr1.z, gr1.w, hA.w, lA.w);
            splitH(gr2.x, gr2.y, hB.x, lB.x); splitH(gr2.z, gr2.w, hB.y, lB.y);
            splitH(gr3.x, gr3.y, hB.z, lB.z); splitH(gr3.z, gr3.w, hB.w, lB.w);
            uint32_t o = (uint32_t)(((c + 1) & 1) * 16384);
            *(uint4*)(smA + pOffA + o)        = hA;
            *(uint4*)(smA + pOffA + o + 8192) = lA;
            *(uint4*)(smA + pOffB + o)        = hB;
            *(uint4*)(smA + pOffB + o + 8192) = lB;
        }
        __syncthreads();
    }

    // ---- epilogue arrays carved from dynamic smem (aliased over dead A bufs) ----
    float (*sS)[66] = (float (*)[66])smA;
    float* sBp = (float*)(smA + 16896);
    float* sPp = (float*)(smA + 17152);
    float* sCp = (float*)(smA + 17408);

    // ks=1 warps write their combined partials; load bias / zero accumulators
    if (ks == 1) {
#pragma unroll
        for (int s = 0; s < 2; ++s) {
            int rr = mg * 32 + s * 16 + (lane >> 2);
#pragma unroll
            for (int t = 0; t < 4; ++t) {
                int cc = ng * 32 + t * 8 + 2 * q;
                *(float2*)&sS[rr][cc] = make_float2(
                    acc[s][t][0] + accL[s][t][0] * LINV,
                    acc[s][t][1] + accL[s][t][1] * LINV);
                *(float2*)&sS[rr + 8][cc] = make_float2(
                    acc[s][t][2] + accL[s][t][2] * LINV,
                    acc[s][t][3] + accL[s][t][3] * LINV);
            }
        }
    }
    if (tid < 64) { sBp[tid] = g_bias[tid]; sPp[tid] = 0.0f; sCp[tid] = 0.0f; }
    __syncthreads();
    if (ks == 0) {
#pragma unroll
        for (int s = 0; s < 2; ++s) {
            int rr = mg * 32 + s * 16 + (lane >> 2);
#pragma unroll
            for (int t = 0; t < 4; ++t) {
                int cc = ng * 32 + t * 8 + 2 * q;
                float2 p0 = *(float2*)&sS[rr][cc];
                float2 p1 = *(float2*)&sS[rr + 8][cc];
                *(float2*)&sS[rr][cc] = make_float2(
                    p0.x + acc[s][t][0] + accL[s][t][0] * LINV,
                    p0.y + acc[s][t][1] + accL[s][t][1] * LINV);
                *(float2*)&sS[rr + 8][cc] = make_float2(
                    p1.x + acc[s][t][2] + accL[s][t][2] * LINV,
                    p1.y + acc[s][t][3] + accL[s][t][3] * LINV);
            }
        }
    }
    __syncthreads();

    // ---- per-token epilogue (threads 0..63, one token each) ----
    if (tid < BM) {
        float a = -1e30f, b = -1e30f;
        int ai = 0, bi = 0;
#pragma unroll
        for (int j = 0; j < 64; ++j) {
            float s = sS[tid][j] + sBp[j];
            sS[tid][j] = s;
            if (s > a)      { b = a; bi = ai; a = s; ai = j; }
            else if (s > b) { b = s; bi = j; }
        }
        float sum = 0.0f;
#pragma unroll
        for (int j = 0; j < 64; ++j) {
            float e = __expf(sS[tid][j] - a);
            sS[tid][j] = e;
            sum += e;
        }
        float inv = 1.0f / sum;
#pragma unroll
        for (int j = 0; j < 64; ++j) sS[tid][j] *= inv;

        int tok = tokBase + tid;
        float tt = __expf(b - a);
        float w1 = 1.0f / (1.0f + tt);
        out[2 * tok]     = w1;
        out[2 * tok + 1] = tt * w1;
        out[2 * T + 2 * tok]     = (float)ai;
        out[2 * T + 2 * tok + 1] = (float)bi;
        atomicAdd(&sCp[ai], 1.0f);
        atomicAdd(&sCp[bi], 1.0f);
    }
    __syncthreads();

    // ---- per-expert prob column sums (all 256 threads, 4 slices of 16 rows) ----
    {
        int e = tid & 63, sl = tid >> 6;
        float s = 0.0f;
#pragma unroll
        for (int i = 0; i < 16; ++i)
            s += sS[sl * 16 + i][e];
        atomicAdd(&sPp[e], s);
    }
    __syncthreads();
    if (tid < E) {
        atomicAdd(&g_psum[tid], sPp[tid]);
        atomicAdd(&g_cnt[tid], sCp[tid]);
    }

    // ---- last CTA computes aux loss (sRed aliases sBp) ----
    if (tid == 0) {
        __threadfence();
        unsigned v = atomicAdd(&g_done, 1u);
        s_last = (v == gridDim.x - 1) ? 1u : 0u;
    }
    __syncthreads();
    float* sRed = sBp;
    if (s_last) {
        if (tid < 64) sRed[tid] = g_cnt[tid] * g_psum[tid];
    }
    __syncthreads();
    if (s_last && tid < 32) {
        float v = sRed[tid] + sRed[tid + 32];
#pragma unroll
        for (int off = 16; off > 0; off >>= 1)
            v += __shfl_xor_sync(0xffffffffu, v, off);
        if (tid == 0) {
            float invT = 1.0f / (float)T;
            out[4 * T] = v * 64.0f * invT * invT;
        }
    }
}

// ---------------------------------------------------------------------------
extern "C" void kernel_launch(void* const* d_in, const int* in_sizes, int n_in,
                              void* d_out, int out_size) {
    const float* x      = (const float*)d_in[0];
    const float* gw     = (const float*)d_in[1];
    const float* rep    = (const float*)d_in[2];
    const float* loads  = (const float*)d_in[3];
    const float* counts = (const float*)d_in[4];
    const int*   total  = (const int*)d_in[5];
    float* out = (float*)d_out;

    int T = in_sizes[0] / H;   // 16384

    cudaFuncSetAttribute(gemm_kernel, cudaFuncAttributeMaxDynamicSharedMemorySize, SMEM_DYN);

    wprep_kernel<<<NKK * 8 * 32 / 256, 256>>>(gw, rep, loads, counts, total);
    gemm_kernel<<<T / BM, 256, SMEM_DYN>>>(x, out, T);
}